// round 15
// baseline (speedup 1.0000x reference)
#include <cuda_runtime.h>
#include <cuda_bf16.h>
#include <cstdint>

#define Bv 4
#define Sv 2048
#define Dv 1024
#define NBv 513
#define KxA 2048           // A = [x_hi | x_lo]
#define KxB 2048           // B = [w_hi | w_lo]
#define NCH 48             // logical K chunks (hi*hi, hi*lo, lo*hi)
#define NOUT 3200          // padded GEMM output width (3*1026 -> 25*128)
#define NROW 8192          // Bv*Sv
#define NCHK 32            // scan chunks (64 rows each)
#define PI_F 3.14159265358979323846f

// ---------------- static device scratch (allocation-free rule) ----------------
__device__ float g_qkv2[(size_t)NROW * NOUT];        // 104.8 MB: spectra q|k|v
__device__ float2 g_kvh[(size_t)NROW * NBv];         // 33.6 MB, [row][bin]
__device__ float2 g_x[(size_t)NROW * NBv];           // 33.6 MB, [row][bin]
__device__ float2 g_tot[Bv * NCHK * NBv];            // chunk sums
__device__ __align__(16) __nv_bfloat16 g_A2[(size_t)NROW * KxA];     // 32 MB
__device__ __align__(16) __nv_bfloat16 g_B2[(size_t)NOUT * KxB];     // 13.1 MB
__device__ float g_Wt[3 * Dv * Dv];                  // 12.6 MB, W transposed
__device__ float2 g_Bc2[(size_t)3 * NBv * Dv];       // 12.6 MB, What [z][n][d]

__device__ __forceinline__ float2 cmul(float2 a, float2 b) {
    return make_float2(a.x * b.x - a.y * b.y, a.x * b.y + a.y * b.x);
}

__device__ __forceinline__ uint32_t smem_u32(const void* p) {
    uint32_t a;
    asm("{ .reg .u64 t; cvta.to.shared.u64 t, %1; cvt.u32.u64 %0, t; }" : "=r"(a) : "l"(p));
    return a;
}
__device__ __forceinline__ void cp16(uint32_t s, const void* g) {
    asm volatile("cp.async.cg.shared.global [%0], [%1], 16;" :: "r"(s), "l"(g));
}
#define CP_COMMIT() asm volatile("cp.async.commit_group;" ::: "memory")
#define CP_WAIT(n)  asm volatile("cp.async.wait_group %0;" :: "n"(n) : "memory")

__device__ __forceinline__ void mma16816(float* c, const uint32_t* a, const uint32_t* b) {
    asm volatile(
        "mma.sync.aligned.m16n8k16.row.col.f32.bf16.bf16.f32 "
        "{%0,%1,%2,%3}, {%4,%5,%6,%7}, {%8,%9}, {%0,%1,%2,%3};"
        : "+f"(c[0]), "+f"(c[1]), "+f"(c[2]), "+f"(c[3])
        : "r"(a[0]), "r"(a[1]), "r"(a[2]), "r"(a[3]), "r"(b[0]), "r"(b[1]));
}
__device__ __forceinline__ void ldm_x4(uint32_t* r, uint32_t addr) {
    asm volatile("ldmatrix.sync.aligned.m8n8.x4.shared.b16 {%0,%1,%2,%3}, [%4];"
        : "=r"(r[0]), "=r"(r[1]), "=r"(r[2]), "=r"(r[3]) : "r"(addr));
}

// ---------------- 1024-pt radix-4 Stockham FFT in shared memory ---------------
// NST=5: full FFT, result in bB. NST=4: partial, result back in bA.
template<int NST>
__device__ __forceinline__ void fft1024_r4(float2* bA, float2* bB, const float2* TW,
                                           int tid, int inverse)
{
    float2* in = bA;
    float2* out = bB;
    #pragma unroll
    for (int st = 0; st < NST; st++) {
        const int Ns = 1 << (2 * st);
        float2 v0 = in[tid];
        float2 v1 = in[tid + 256];
        float2 v2 = in[tid + 512];
        float2 v3 = in[tid + 768];
        const int t = tid & (Ns - 1);
        if (st > 0) {
            const int ti = t << (8 - 2 * st);
            float2 w1 = TW[ti], w2 = TW[2 * ti], w3 = TW[3 * ti];
            if (inverse) { w1.y = -w1.y; w2.y = -w2.y; w3.y = -w3.y; }
            v1 = cmul(v1, w1); v2 = cmul(v2, w2); v3 = cmul(v3, w3);
        }
        float2 a  = make_float2(v0.x + v2.x, v0.y + v2.y);
        float2 bq = make_float2(v0.x - v2.x, v0.y - v2.y);
        float2 c  = make_float2(v1.x + v3.x, v1.y + v3.y);
        float2 d  = make_float2(v1.x - v3.x, v1.y - v3.y);
        float2 dr = inverse ? make_float2(-d.y, d.x) : make_float2(d.y, -d.x);
        const int idx = ((tid >> (2 * st)) << (2 * st + 2)) + t;
        out[idx]          = make_float2(a.x + c.x,  a.y + c.y);
        out[idx + Ns]     = make_float2(bq.x + dr.x, bq.y + dr.y);
        out[idx + 2 * Ns] = make_float2(a.x - c.x,  a.y - c.y);
        out[idx + 3 * Ns] = make_float2(bq.x - dr.x, bq.y - dr.y);
        __syncthreads();
        float2* tmp = in; in = out; out = tmp;
    }
}

__device__ __forceinline__ void fill_tw768(float2* TW, int tid)
{
    for (int t = tid; t < 768; t += 256) {
        float sv, cv;
        __sincosf(-(2.f * PI_F) * (float)t * (1.f / 1024.f), &sv, &cv);
        TW[t] = make_float2(cv, sv);
    }
}

// ================= weight prep: transpose, FFT, bf16 hi/lo ====================
__global__ void transp_w(const float* __restrict__ W0,
                         const float* __restrict__ W1,
                         const float* __restrict__ W2)
{
    __shared__ float t[32][33];
    const float* W = (blockIdx.z == 0) ? W0 : (blockIdx.z == 1) ? W1 : W2;
    const int tx = threadIdx.x, ty = threadIdx.y;
    const int x0 = blockIdx.x * 32, y0 = blockIdx.y * 32;
    #pragma unroll
    for (int j = 0; j < 4; j++)
        t[ty + j * 8][tx] = W[(size_t)(y0 + ty + j * 8) * Dv + x0 + tx];
    __syncthreads();
    float* Wt = g_Wt + (size_t)blockIdx.z * Dv * Dv;
    #pragma unroll
    for (int j = 0; j < 4; j++)
        Wt[(size_t)(x0 + ty + j * 8) * Dv + y0 + tx] = t[tx][ty + j * 8];
}

__global__ void fft_w()
{
    __shared__ float2 bA[1024], bB[1024], TW[768];
    const int tid = threadIdx.x;
    const int row0 = blockIdx.x * 2;
    const int z = row0 >> 10, d0 = row0 & 1023;
    const float* w0 = g_Wt + (size_t)row0 * Dv;
    const float* w1 = w0 + Dv;

    fill_tw768(TW, tid);
    for (int d = tid; d < 1024; d += 256)
        bA[d] = make_float2(w0[d], w1[d]);
    __syncthreads();
    fft1024_r4<5>(bA, bB, TW, tid, 0);

    float2* dst = g_Bc2 + (size_t)z * NBv * Dv;
    for (int n = tid; n < 513; n += 256) {
        float2 z0 = bB[n];
        float2 z1 = bB[(1024 - n) & 1023];
        float2 A = make_float2(0.5f * (z0.x + z1.x), 0.5f * (z0.y - z1.y));
        float2 Bc = make_float2(0.5f * (z0.y + z1.y), 0.5f * (z1.x - z0.x));
        dst[(size_t)n * Dv + d0] = A;
        dst[(size_t)n * Dv + d0 + 1] = Bc;
    }
}

// B2 row: [0:1024]=hi(w), [1024:2048]=lo(w)
__global__ void convert_B()
{
    const int r = blockIdx.x;
    const int tid = threadIdx.x;
    __nv_bfloat16* row = g_B2 + (size_t)r * KxB;
    if (r >= 3 * 1026) {
        for (int d = tid; d < 1024; d += 256) {
            row[d] = __float2bfloat16_rn(0.f);
            row[1024 + d] = __float2bfloat16_rn(0.f);
        }
        return;
    }
    const int z = r / 1026, rr = r % 1026;
    const int n = rr >> 1, im = rr & 1;
    const float2* src = g_Bc2 + ((size_t)z * NBv + n) * Dv;
    for (int d = tid; d < 1024; d += 256) {
        float2 c = src[d];
        float v = im ? c.y : c.x;
        __nv_bfloat16 h = __float2bfloat16_rn(v);
        __nv_bfloat16 l = __float2bfloat16_rn(v - __bfloat162float(h));
        row[d] = h;
        row[1024 + d] = l;
    }
}

// A2[m, 0:1024]=hi(x), [1024:2048]=lo(x)
__global__ void convert_x(const float* __restrict__ X)
{
    size_t i4 = (size_t)blockIdx.x * blockDim.x + threadIdx.x;
    float4 x = ((const float4*)X)[i4];
    size_t m = i4 >> 8;
    size_t kc = (i4 & 255) * 4;
    __nv_bfloat16 h0 = __float2bfloat16_rn(x.x), h1 = __float2bfloat16_rn(x.y);
    __nv_bfloat16 h2 = __float2bfloat16_rn(x.z), h3 = __float2bfloat16_rn(x.w);
    __nv_bfloat16 l0 = __float2bfloat16_rn(x.x - __bfloat162float(h0));
    __nv_bfloat16 l1 = __float2bfloat16_rn(x.y - __bfloat162float(h1));
    __nv_bfloat16 l2 = __float2bfloat16_rn(x.z - __bfloat162float(h2));
    __nv_bfloat16 l3 = __float2bfloat16_rn(x.w - __bfloat162float(h3));
    __nv_bfloat16* row = g_A2 + m * KxA;
    __nv_bfloat162 ha = __halves2bfloat162(h0, h1), hb = __halves2bfloat162(h2, h3);
    __nv_bfloat162 la = __halves2bfloat162(l0, l1), lb = __halves2bfloat162(l2, l3);
    *(__nv_bfloat162*)(row + kc) = ha;          *(__nv_bfloat162*)(row + kc + 2) = hb;
    *(__nv_bfloat162*)(row + 1024 + kc) = la;   *(__nv_bfloat162*)(row + 1024 + kc + 2) = lb;
}

// ================= HMMA bf16 GEMM: g_qkv2 = A2(+) @ B2(+)^T ===================
// LOCKED pipeline (round 11): CTA 128x128, 256 threads, 3-stage, 2 CTA/SM.
// Offset remaps only:
//   A chunk aIdx = (ch<32) ? ch&15 : ch-16   (hi,hi,...,lo)
//   B chunk bIdx = (ch<32) ? ch     : ch-32   (hi,lo,hi)
// ch 0-15: hi*hi; ch 16-31: hi*lo; ch 32-47: lo*hi.
#define BM 128
#define BN 128
#define BKC 64
#define STG_A (BM * 144)      // 18432 B
#define STAGE (2 * STG_A)     // 36864 B (A then B)
#define GEMM_SMEM (3 * STAGE) // 110592 B; 2 CTA/SM

__global__ __launch_bounds__(256, 2) void gemm_mma()
{
    extern __shared__ char smem[];
    const uint32_t sb = smem_u32(smem);
    const int tid = threadIdx.x;
    const int bm = blockIdx.y * BM;
    const int bn = blockIdx.x * BN;

    const int lane = tid & 31, wid = tid >> 5;
    const int g = lane >> 2, tig = lane & 3;
    const int wm = (wid >> 2) * 64, wn = (wid & 3) * 32;

    const int arow = lane & 15;
    const int ahalf = (lane >> 4) & 1;
    const int brow = (lane & 7) + ((lane >> 4) << 3);
    const int bhalf = (lane >> 3) & 1;

    float acc[4][4][4];
    #pragma unroll
    for (int mt = 0; mt < 4; mt++)
        #pragma unroll
        for (int nt = 0; nt < 4; nt++)
            #pragma unroll
            for (int i = 0; i < 4; i++) acc[mt][nt][i] = 0.f;

    auto issue = [&](int ch) {
        const int stg = ch % 3;
        const uint32_t offA = sb + stg * STAGE;
        const uint32_t offB = offA + STG_A;
        const int aIdx = (ch < 32) ? (ch & 15) : (ch - 16);   // in [0,32)
        const int bIdx = (ch < 32) ? ch : (ch - 32);          // in [0,32)
        const size_t koffA = (size_t)aIdx * BKC;
        const size_t koffB = (size_t)bIdx * BKC;
        #pragma unroll
        for (int t = 0; t < 4; t++) {
            int idx = tid + t * 256;
            int r = idx >> 3, c = idx & 7;
            cp16(offA + r * 144 + c * 16, g_A2 + (size_t)(bm + r) * KxA + koffA + c * 8);
        }
        #pragma unroll
        for (int t = 0; t < 4; t++) {
            int idx = tid + t * 256;
            int r = idx >> 3, c = idx & 7;
            cp16(offB + r * 144 + c * 16, g_B2 + (size_t)(bn + r) * KxB + koffB + c * 8);
        }
        CP_COMMIT();
    };

    issue(0);
    issue(1);
    for (int ch = 0; ch < NCH; ch++) {
        if (ch + 1 < NCH) { CP_WAIT(1); } else { CP_WAIT(0); }
        __syncthreads();                       // single barrier per chunk

        const int stg = ch % 3;
        const uint32_t sA32 = sb + stg * STAGE;
        const uint32_t sB32 = sA32 + STG_A;
        #pragma unroll
        for (int ks = 0; ks < 4; ks++) {
            uint32_t af[4][4], bfr[2][4];
            #pragma unroll
            for (int mt = 0; mt < 4; mt++)
                ldm_x4(af[mt], sA32 + (wm + mt * 16 + arow) * 144 + ks * 32 + ahalf * 16);
            #pragma unroll
            for (int np = 0; np < 2; np++)
                ldm_x4(bfr[np], sB32 + (wn + np * 16 + brow) * 144 + ks * 32 + bhalf * 16);
            #pragma unroll
            for (int mt = 0; mt < 4; mt++)
                #pragma unroll
                for (int nt = 0; nt < 4; nt++)
                    mma16816(acc[mt][nt], af[mt], &bfr[nt >> 1][(nt & 1) * 2]);
        }

        if (ch + 2 < NCH) issue(ch + 2);       // writes stage (ch+2)%3: disjoint
    }

    #pragma unroll
    for (int mt = 0; mt < 4; mt++) {
        #pragma unroll
        for (int nt = 0; nt < 4; nt++) {
            int row = bm + wm + mt * 16 + g;
            int col = bn + wn + nt * 8 + 2 * tig;
            *(float2*)(g_qkv2 + (size_t)row * NOUT + col) =
                make_float2(acc[mt][nt][0], acc[mt][nt][1]);
            *(float2*)(g_qkv2 + (size_t)(row + 8) * NOUT + col) =
                make_float2(acc[mt][nt][2], acc[mt][nt][3]);
        }
    }
}

// ---------------- spectral prep: coalesced kvhat + conj-norm Q ----------------
__global__ void spectral_prep()
{
    const int row = blockIdx.x;                 // b*2048 + s
    const int tid = threadIdx.x;
    const float2* base = (const float2*)(g_qkv2 + (size_t)row * NOUT);
    const float2* qr = base;
    const float2* kr = base + 513;
    const float2* vr = base + 1026;
    float2* kvout = g_kvh + (size_t)row * NBv;
    float2* qnout = g_x + (size_t)row * NBv;

    for (int n = tid; n < 513; n += 256) {
        float2 K = kr[n], V = vr[n], Q = qr[n];
        float ik = 1.f / (sqrtf(K.x * K.x + K.y * K.y) + 1e-8f);
        float iq = 1.f / (sqrtf(Q.x * Q.x + Q.y * Q.y) + 1e-8f);
        float2 Ku = make_float2(K.x * ik, K.y * ik);
        kvout[n] = cmul(Ku, V);
        qnout[n] = make_float2(Q.x * iq, -Q.y * iq);
    }
}

// ---------------- chunked scan along s (layout [row][bin], 64-row chunks) -----
__global__ void scan_pass1()
{
    const int tid = threadIdx.x;
    if (tid >= 171) return;
    const int bin = blockIdx.x * 171 + tid;     // 3*171 = 513
    const int chunk = blockIdx.y, b = blockIdx.z;
    const float2* p = g_kvh + ((size_t)(b * Sv + chunk * 64)) * NBv + bin;
    float2 acc = make_float2(0.f, 0.f);
    #pragma unroll 4
    for (int r = 0; r < 64; r++) {
        float2 v = *p;
        acc.x += v.x; acc.y += v.y;
        p += NBv;
    }
    g_tot[((size_t)b * NCHK + chunk) * NBv + bin] = acc;
}

__global__ void scan_pass2()
{
    const int tid = threadIdx.x;
    if (tid >= 171) return;
    const int bin = blockIdx.x * 171 + tid;
    const int chunk = blockIdx.y, b = blockIdx.z;

    float2 acc = make_float2(0.f, 0.f);
    for (int c = 0; c < chunk; c++) {
        float2 t = g_tot[((size_t)b * NCHK + c) * NBv + bin];
        acc.x += t.x; acc.y += t.y;
    }
    const float2* p = g_kvh + ((size_t)(b * Sv + chunk * 64)) * NBv + bin;
    float2* xp = g_x + ((size_t)(b * Sv + chunk * 64)) * NBv + bin;
    #pragma unroll 4
    for (int r = 0; r < 64; r++) {
        float2 v = *p;
        acc.x += v.x; acc.y += v.y;
        *xp = cmul(acc, *xp);
        p += NBv; xp += NBv;
    }
}

// ---------------- inverse FFT, two rows packed, last stage -> gmem ------------
__global__ void out_kernel(float* __restrict__ out)
{
    __shared__ float2 bA[1024], bB[1024], TW[768];
    const int tid = threadIdx.x;
    const int row0 = blockIdx.x * 2;

    fill_tw768(TW, tid);
    const float2* X0 = g_x + (size_t)row0 * NBv;
    const float2* X1 = X0 + NBv;
    for (int d = tid; d < 1024; d += 256) {
        float2 x0, x1;
        if (d <= 512) { x0 = X0[d]; x1 = X1[d]; }
        else {
            float2 a0 = X0[1024 - d], a1 = X1[1024 - d];
            x0 = make_float2(a0.x, -a0.y);
            x1 = make_float2(a1.x, -a1.y);
        }
        bA[d] = make_float2(x0.x - x1.y, x0.y + x1.x);   // Z = X0 + i*X1
    }
    __syncthreads();
    fft1024_r4<4>(bA, bB, TW, tid, 1);        // 4 stages; result back in bA

    // final stage (st=4, Ns=256) in registers, write gmem directly
    float* o0 = out + (size_t)row0 * Dv;
    float* o1 = o0 + Dv;
    const float scale = 1.f / 1024.f;
    {
        float2 v0 = bA[tid], v1 = bA[tid + 256], v2 = bA[tid + 512], v3 = bA[tid + 768];
        float2 w1 = TW[tid], w2 = TW[2 * tid], w3 = TW[3 * tid];
        w1.y = -w1.y; w2.y = -w2.y; w3.y = -w3.y;        // inverse twiddles
        v1 = cmul(v1, w1); v2 = cmul(v2, w2); v3 = cmul(v3, w3);
        float2 a  = make_float2(v0.x + v2.x, v0.y + v2.y);
        float2 bq = make_float2(v0.x - v2.x, v0.y - v2.y);
        float2 c  = make_float2(v1.x + v3.x, v1.y + v3.y);
        float2 d  = make_float2(v1.x - v3.x, v1.y - v3.y);
        float2 dr = make_float2(-d.y, d.x);              // inverse rotation
        float2 r0 = make_float2(a.x + c.x,  a.y + c.y);
        float2 r1 = make_float2(bq.x + dr.x, bq.y + dr.y);
        float2 r2 = make_float2(a.x - c.x,  a.y - c.y);
        float2 r3 = make_float2(bq.x - dr.x, bq.y - dr.y);
        o0[tid]       = r0.x * scale;  o1[tid]       = r0.y * scale;
        o0[tid + 256] = r1.x * scale;  o1[tid + 256] = r1.y * scale;
        o0[tid + 512] = r2.x * scale;  o1[tid + 512] = r2.y * scale;
        o0[tid + 768] = r3.x * scale;  o1[tid + 768] = r3.y * scale;
    }
}

// ---------------- launch ------------------------------------------------------
extern "C" void kernel_launch(void* const* d_in, const int* in_sizes, int n_in,
                              void* d_out, int out_size)
{
    (void)in_sizes; (void)n_in; (void)out_size;
    const float* x  = (const float*)d_in[0];
    const float* Wq = (const float*)d_in[1];
    const float* Wk = (const float*)d_in[2];
    const float* Wv = (const float*)d_in[3];
    float* out = (float*)d_out;

    cudaFuncSetAttribute(gemm_mma, cudaFuncAttributeMaxDynamicSharedMemorySize, GEMM_SMEM);

    transp_w<<<dim3(32, 32, 3), dim3(32, 8)>>>(Wq, Wk, Wv);
    fft_w<<<(3 * Dv) / 2, 256>>>();
    convert_B<<<NOUT, 256>>>();
    convert_x<<<(NROW * Dv / 4) / 256, 256>>>(x);

    dim3 gg(NOUT / BN, NROW / BM);    // (25, 64)
    gemm_mma<<<gg, 256, GEMM_SMEM>>>();

    spectral_prep<<<NROW, 256>>>();
    scan_pass1<<<dim3(3, NCHK, Bv), 192>>>();
    scan_pass2<<<dim3(3, NCHK, Bv), 192>>>();
    out_kernel<<<NROW / 2, 256>>>(out);
}

// round 16
// speedup vs baseline: 1.0423x; 1.0423x over previous
#include <cuda_runtime.h>
#include <cuda_bf16.h>
#include <cstdint>

#define Bv 4
#define Sv 2048
#define Dv 1024
#define NBv 513
#define KxA 2048           // A = [x_hi | x_lo]
#define Kx 3072            // B K-extent (hi|lo|hi), 48 chunks
#define NOUT 3200          // padded GEMM output width (3*1026 -> 25*128)
#define NROW 8192          // Bv*Sv
#define NCHK 32            // scan chunks (64 rows each)
#define PI_F 3.14159265358979323846f

// ---------------- static device scratch (allocation-free rule) ----------------
__device__ float g_qkv2[(size_t)NROW * NOUT];        // 104.8 MB: spectra q|k|v
__device__ float2 g_kvh[(size_t)NROW * NBv];         // 33.6 MB, [row][bin]; scanned in place
__device__ float2 g_tot[Bv * NCHK * NBv];            // chunk sums
__device__ __align__(16) __nv_bfloat16 g_A2[(size_t)NROW * KxA];     // 32 MB
__device__ __align__(16) __nv_bfloat16 g_B3[(size_t)NOUT * Kx];      // 19.7 MB
__device__ float g_Wt[3 * Dv * Dv];                  // 12.6 MB, W transposed
__device__ float2 g_Bc2[(size_t)3 * NBv * Dv];       // 12.6 MB, What [z][n][d]

__device__ __forceinline__ float2 cmul(float2 a, float2 b) {
    return make_float2(a.x * b.x - a.y * b.y, a.x * b.y + a.y * b.x);
}

__device__ __forceinline__ uint32_t smem_u32(const void* p) {
    uint32_t a;
    asm("{ .reg .u64 t; cvta.to.shared.u64 t, %1; cvt.u32.u64 %0, t; }" : "=r"(a) : "l"(p));
    return a;
}
__device__ __forceinline__ void cp16(uint32_t s, const void* g) {
    asm volatile("cp.async.cg.shared.global [%0], [%1], 16;" :: "r"(s), "l"(g));
}
#define CP_COMMIT() asm volatile("cp.async.commit_group;" ::: "memory")
#define CP_WAIT(n)  asm volatile("cp.async.wait_group %0;" :: "n"(n) : "memory")

__device__ __forceinline__ void mma16816(float* c, const uint32_t* a, const uint32_t* b) {
    asm volatile(
        "mma.sync.aligned.m16n8k16.row.col.f32.bf16.bf16.f32 "
        "{%0,%1,%2,%3}, {%4,%5,%6,%7}, {%8,%9}, {%0,%1,%2,%3};"
        : "+f"(c[0]), "+f"(c[1]), "+f"(c[2]), "+f"(c[3])
        : "r"(a[0]), "r"(a[1]), "r"(a[2]), "r"(a[3]), "r"(b[0]), "r"(b[1]));
}
__device__ __forceinline__ void ldm_x4(uint32_t* r, uint32_t addr) {
    asm volatile("ldmatrix.sync.aligned.m8n8.x4.shared.b16 {%0,%1,%2,%3}, [%4];"
        : "=r"(r[0]), "=r"(r[1]), "=r"(r[2]), "=r"(r[3]) : "r"(addr));
}

// ---------------- 1024-pt radix-4 Stockham FFT in shared memory ---------------
// NST=5: full FFT, result in bB. NST=4: partial, result back in bA.
template<int NST>
__device__ __forceinline__ void fft1024_r4(float2* bA, float2* bB, const float2* TW,
                                           int tid, int inverse)
{
    float2* in = bA;
    float2* out = bB;
    #pragma unroll
    for (int st = 0; st < NST; st++) {
        const int Ns = 1 << (2 * st);
        float2 v0 = in[tid];
        float2 v1 = in[tid + 256];
        float2 v2 = in[tid + 512];
        float2 v3 = in[tid + 768];
        const int t = tid & (Ns - 1);
        if (st > 0) {
            const int ti = t << (8 - 2 * st);
            float2 w1 = TW[ti], w2 = TW[2 * ti], w3 = TW[3 * ti];
            if (inverse) { w1.y = -w1.y; w2.y = -w2.y; w3.y = -w3.y; }
            v1 = cmul(v1, w1); v2 = cmul(v2, w2); v3 = cmul(v3, w3);
        }
        float2 a  = make_float2(v0.x + v2.x, v0.y + v2.y);
        float2 bq = make_float2(v0.x - v2.x, v0.y - v2.y);
        float2 c  = make_float2(v1.x + v3.x, v1.y + v3.y);
        float2 d  = make_float2(v1.x - v3.x, v1.y - v3.y);
        float2 dr = inverse ? make_float2(-d.y, d.x) : make_float2(d.y, -d.x);
        const int idx = ((tid >> (2 * st)) << (2 * st + 2)) + t;
        out[idx]          = make_float2(a.x + c.x,  a.y + c.y);
        out[idx + Ns]     = make_float2(bq.x + dr.x, bq.y + dr.y);
        out[idx + 2 * Ns] = make_float2(a.x - c.x,  a.y - c.y);
        out[idx + 3 * Ns] = make_float2(bq.x - dr.x, bq.y - dr.y);
        __syncthreads();
        float2* tmp = in; in = out; out = tmp;
    }
}

__device__ __forceinline__ void fill_tw768(float2* TW, int tid)
{
    for (int t = tid; t < 768; t += 256) {
        float sv, cv;
        __sincosf(-(2.f * PI_F) * (float)t * (1.f / 1024.f), &sv, &cv);
        TW[t] = make_float2(cv, sv);
    }
}

// ================= weight prep: transpose, FFT, bf16 hi/lo ====================
__global__ void transp_w(const float* __restrict__ W0,
                         const float* __restrict__ W1,
                         const float* __restrict__ W2)
{
    __shared__ float t[32][33];
    const float* W = (blockIdx.z == 0) ? W0 : (blockIdx.z == 1) ? W1 : W2;
    const int tx = threadIdx.x, ty = threadIdx.y;
    const int x0 = blockIdx.x * 32, y0 = blockIdx.y * 32;
    #pragma unroll
    for (int j = 0; j < 4; j++)
        t[ty + j * 8][tx] = W[(size_t)(y0 + ty + j * 8) * Dv + x0 + tx];
    __syncthreads();
    float* Wt = g_Wt + (size_t)blockIdx.z * Dv * Dv;
    #pragma unroll
    for (int j = 0; j < 4; j++)
        Wt[(size_t)(x0 + ty + j * 8) * Dv + y0 + tx] = t[tx][ty + j * 8];
}

__global__ void fft_w()
{
    __shared__ float2 bA[1024], bB[1024], TW[768];
    const int tid = threadIdx.x;
    const int row0 = blockIdx.x * 2;
    const int z = row0 >> 10, d0 = row0 & 1023;
    const float* w0 = g_Wt + (size_t)row0 * Dv;
    const float* w1 = w0 + Dv;

    fill_tw768(TW, tid);
    for (int d = tid; d < 1024; d += 256)
        bA[d] = make_float2(w0[d], w1[d]);
    __syncthreads();
    fft1024_r4<5>(bA, bB, TW, tid, 0);

    float2* dst = g_Bc2 + (size_t)z * NBv * Dv;
    for (int n = tid; n < 513; n += 256) {
        float2 z0 = bB[n];
        float2 z1 = bB[(1024 - n) & 1023];
        float2 A = make_float2(0.5f * (z0.x + z1.x), 0.5f * (z0.y - z1.y));
        float2 Bc = make_float2(0.5f * (z0.y + z1.y), 0.5f * (z1.x - z0.x));
        dst[(size_t)n * Dv + d0] = A;
        dst[(size_t)n * Dv + d0 + 1] = Bc;
    }
}

__global__ void convert_B()
{
    const int r = blockIdx.x;
    const int tid = threadIdx.x;
    __nv_bfloat16* row = g_B3 + (size_t)r * Kx;
    if (r >= 3 * 1026) {
        for (int d = tid; d < 1024; d += 256) {
            row[d] = __float2bfloat16_rn(0.f);
            row[1024 + d] = __float2bfloat16_rn(0.f);
            row[2048 + d] = __float2bfloat16_rn(0.f);
        }
        return;
    }
    const int z = r / 1026, rr = r % 1026;
    const int n = rr >> 1, im = rr & 1;
    const float2* src = g_Bc2 + ((size_t)z * NBv + n) * Dv;
    for (int d = tid; d < 1024; d += 256) {
        float2 c = src[d];
        float v = im ? c.y : c.x;
        __nv_bfloat16 h = __float2bfloat16_rn(v);
        __nv_bfloat16 l = __float2bfloat16_rn(v - __bfloat162float(h));
        row[d] = h;
        row[1024 + d] = l;
        row[2048 + d] = h;
    }
}

// A2[m, 0:1024]=hi(x), [1024:2048]=lo(x)
__global__ void convert_x(const float* __restrict__ X)
{
    size_t i4 = (size_t)blockIdx.x * blockDim.x + threadIdx.x;
    float4 x = ((const float4*)X)[i4];
    size_t m = i4 >> 8;
    size_t kc = (i4 & 255) * 4;
    __nv_bfloat16 h0 = __float2bfloat16_rn(x.x), h1 = __float2bfloat16_rn(x.y);
    __nv_bfloat16 h2 = __float2bfloat16_rn(x.z), h3 = __float2bfloat16_rn(x.w);
    __nv_bfloat16 l0 = __float2bfloat16_rn(x.x - __bfloat162float(h0));
    __nv_bfloat16 l1 = __float2bfloat16_rn(x.y - __bfloat162float(h1));
    __nv_bfloat16 l2 = __float2bfloat16_rn(x.z - __bfloat162float(h2));
    __nv_bfloat16 l3 = __float2bfloat16_rn(x.w - __bfloat162float(h3));
    __nv_bfloat16* row = g_A2 + m * KxA;
    __nv_bfloat162 ha = __halves2bfloat162(h0, h1), hb = __halves2bfloat162(h2, h3);
    __nv_bfloat162 la = __halves2bfloat162(l0, l1), lb = __halves2bfloat162(l2, l3);
    *(__nv_bfloat162*)(row + kc) = ha;          *(__nv_bfloat162*)(row + kc + 2) = hb;
    *(__nv_bfloat162*)(row + 1024 + kc) = la;   *(__nv_bfloat162*)(row + 1024 + kc + 2) = lb;
}

// ================= HMMA bf16 GEMM: g_qkv2 = A2(+) @ B3^T ======================
// LOCKED pipeline (round 11/14): CTA 128x128, 256 threads, 3-stage, 2 CTA/SM.
// A source remap only: chunk ch reads A chunk (ch<32 ? ch&15 : ch-16).
#define BM 128
#define BN 128
#define BKC 64
#define NCH (Kx / BKC)        // 48
#define STG_A (BM * 144)      // 18432 B
#define STAGE (2 * STG_A)     // 36864 B (A then B)
#define GEMM_SMEM (3 * STAGE) // 110592 B; 2 CTA/SM

__global__ __launch_bounds__(256, 2) void gemm_mma()
{
    extern __shared__ char smem[];
    const uint32_t sb = smem_u32(smem);
    const int tid = threadIdx.x;
    const int bm = blockIdx.y * BM;
    const int bn = blockIdx.x * BN;

    const int lane = tid & 31, wid = tid >> 5;
    const int g = lane >> 2, tig = lane & 3;
    const int wm = (wid >> 2) * 64, wn = (wid & 3) * 32;

    const int arow = lane & 15;
    const int ahalf = (lane >> 4) & 1;
    const int brow = (lane & 7) + ((lane >> 4) << 3);
    const int bhalf = (lane >> 3) & 1;

    float acc[4][4][4];
    #pragma unroll
    for (int mt = 0; mt < 4; mt++)
        #pragma unroll
        for (int nt = 0; nt < 4; nt++)
            #pragma unroll
            for (int i = 0; i < 4; i++) acc[mt][nt][i] = 0.f;

    auto issue = [&](int ch) {
        const int stg = ch % 3;
        const uint32_t offA = sb + stg * STAGE;
        const uint32_t offB = offA + STG_A;
        const int aIdx = (ch < 32) ? (ch & 15) : (ch - 16);   // A chunk in [0,32)
        const size_t koffA = (size_t)aIdx * BKC;
        const size_t koffB = (size_t)ch * BKC;
        #pragma unroll
        for (int t = 0; t < 4; t++) {
            int idx = tid + t * 256;
            int r = idx >> 3, c = idx & 7;
            cp16(offA + r * 144 + c * 16, g_A2 + (size_t)(bm + r) * KxA + koffA + c * 8);
        }
        #pragma unroll
        for (int t = 0; t < 4; t++) {
            int idx = tid + t * 256;
            int r = idx >> 3, c = idx & 7;
            cp16(offB + r * 144 + c * 16, g_B3 + (size_t)(bn + r) * Kx + koffB + c * 8);
        }
        CP_COMMIT();
    };

    issue(0);
    issue(1);
    for (int ch = 0; ch < NCH; ch++) {
        if (ch + 1 < NCH) { CP_WAIT(1); } else { CP_WAIT(0); }
        __syncthreads();                       // single barrier per chunk

        const int stg = ch % 3;
        const uint32_t sA32 = sb + stg * STAGE;
        const uint32_t sB32 = sA32 + STG_A;
        #pragma unroll
        for (int ks = 0; ks < 4; ks++) {
            uint32_t af[4][4], bfr[2][4];
            #pragma unroll
            for (int mt = 0; mt < 4; mt++)
                ldm_x4(af[mt], sA32 + (wm + mt * 16 + arow) * 144 + ks * 32 + ahalf * 16);
            #pragma unroll
            for (int np = 0; np < 2; np++)
                ldm_x4(bfr[np], sB32 + (wn + np * 16 + brow) * 144 + ks * 32 + bhalf * 16);
            #pragma unroll
            for (int mt = 0; mt < 4; mt++)
                #pragma unroll
                for (int nt = 0; nt < 4; nt++)
                    mma16816(acc[mt][nt], af[mt], &bfr[nt >> 1][(nt & 1) * 2]);
        }

        if (ch + 2 < NCH) issue(ch + 2);       // writes stage (ch+2)%3: disjoint
    }

    #pragma unroll
    for (int mt = 0; mt < 4; mt++) {
        #pragma unroll
        for (int nt = 0; nt < 4; nt++) {
            int row = bm + wm + mt * 16 + g;
            int col = bn + wn + nt * 8 + 2 * tig;
            *(float2*)(g_qkv2 + (size_t)row * NOUT + col) =
                make_float2(acc[mt][nt][0], acc[mt][nt][1]);
            *(float2*)(g_qkv2 + (size_t)(row + 8) * NOUT + col) =
                make_float2(acc[mt][nt][2], acc[mt][nt][3]);
        }
    }
}

// ---------------- spectral prep: K,V only -> kvhat (coalesced) ----------------
__global__ void spectral_prep()
{
    const int row = blockIdx.x;                 // b*2048 + s
    const int tid = threadIdx.x;
    const float2* base = (const float2*)(g_qkv2 + (size_t)row * NOUT);
    const float2* kr = base + 513;
    const float2* vr = base + 1026;
    float2* kvout = g_kvh + (size_t)row * NBv;

    for (int n = tid; n < 513; n += 256) {
        float2 K = kr[n], V = vr[n];
        float ik = 1.f / (sqrtf(K.x * K.x + K.y * K.y) + 1e-8f);
        float2 Ku = make_float2(K.x * ik, K.y * ik);
        kvout[n] = cmul(Ku, V);
    }
}

// ---------------- chunked scan along s (layout [row][bin], 64-row chunks) -----
__global__ void scan_pass1()
{
    const int tid = threadIdx.x;
    if (tid >= 171) return;
    const int bin = blockIdx.x * 171 + tid;     // 3*171 = 513
    const int chunk = blockIdx.y, b = blockIdx.z;
    const float2* p = g_kvh + ((size_t)(b * Sv + chunk * 64)) * NBv + bin;
    float2 acc = make_float2(0.f, 0.f);
    #pragma unroll 4
    for (int r = 0; r < 64; r++) {
        float2 v = *p;
        acc.x += v.x; acc.y += v.y;
        p += NBv;
    }
    g_tot[((size_t)b * NCHK + chunk) * NBv + bin] = acc;
}

// pass2: walk chunk adding prefix, write scanned value IN PLACE into g_kvh
__global__ void scan_pass2()
{
    const int tid = threadIdx.x;
    if (tid >= 171) return;
    const int bin = blockIdx.x * 171 + tid;
    const int chunk = blockIdx.y, b = blockIdx.z;

    float2 acc = make_float2(0.f, 0.f);
    for (int c = 0; c < chunk; c++) {
        float2 t = g_tot[((size_t)b * NCHK + c) * NBv + bin];
        acc.x += t.x; acc.y += t.y;
    }
    float2* p = g_kvh + ((size_t)(b * Sv + chunk * 64)) * NBv + bin;
    #pragma unroll 4
    for (int r = 0; r < 64; r++) {
        float2 v = *p;
        acc.x += v.x; acc.y += v.y;
        *p = acc;
        p += NBv;
    }
}

// ------- inverse FFT: inline conj-norm Q multiply, two rows, reg finale -------
__global__ void out_kernel(float* __restrict__ out)
{
    __shared__ float2 bA[1024], bB[1024], TW[768];
    const int tid = threadIdx.x;
    const int row0 = blockIdx.x * 2;

    fill_tw768(TW, tid);
    const float2* kv0 = g_kvh + (size_t)row0 * NBv;
    const float2* kv1 = kv0 + NBv;
    const float2* q0 = (const float2*)(g_qkv2 + (size_t)row0 * NOUT);
    const float2* q1 = (const float2*)(g_qkv2 + (size_t)(row0 + 1) * NOUT);

    for (int d = tid; d < 1024; d += 256) {
        const int n = (d <= 512) ? d : 1024 - d;
        float2 kA = kv0[n], qA = q0[n];
        float2 kB = kv1[n], qB = q1[n];
        float iA = 1.f / (sqrtf(qA.x * qA.x + qA.y * qA.y) + 1e-8f);
        float iB = 1.f / (sqrtf(qB.x * qB.x + qB.y * qB.y) + 1e-8f);
        float2 x0 = cmul(kA, make_float2(qA.x * iA, -qA.y * iA));
        float2 x1 = cmul(kB, make_float2(qB.x * iB, -qB.y * iB));
        if (d > 512) { x0.y = -x0.y; x1.y = -x1.y; }     // Hermitian extension
        bA[d] = make_float2(x0.x - x1.y, x0.y + x1.x);   // Z = X0 + i*X1
    }
    __syncthreads();
    fft1024_r4<4>(bA, bB, TW, tid, 1);        // 4 stages; result back in bA

    // final stage (st=4, Ns=256) in registers, write gmem directly
    float* o0 = out + (size_t)row0 * Dv;
    float* o1 = o0 + Dv;
    const float scale = 1.f / 1024.f;
    {
        float2 v0 = bA[tid], v1 = bA[tid + 256], v2 = bA[tid + 512], v3 = bA[tid + 768];
        float2 w1 = TW[tid], w2 = TW[2 * tid], w3 = TW[3 * tid];
        w1.y = -w1.y; w2.y = -w2.y; w3.y = -w3.y;        // inverse twiddles
        v1 = cmul(v1, w1); v2 = cmul(v2, w2); v3 = cmul(v3, w3);
        float2 a  = make_float2(v0.x + v2.x, v0.y + v2.y);
        float2 bq = make_float2(v0.x - v2.x, v0.y - v2.y);
        float2 c  = make_float2(v1.x + v3.x, v1.y + v3.y);
        float2 d  = make_float2(v1.x - v3.x, v1.y - v3.y);
        float2 dr = make_float2(-d.y, d.x);              // inverse rotation
        float2 r0 = make_float2(a.x + c.x,  a.y + c.y);
        float2 r1 = make_float2(bq.x + dr.x, bq.y + dr.y);
        float2 r2 = make_float2(a.x - c.x,  a.y - c.y);
        float2 r3 = make_float2(bq.x - dr.x, bq.y - dr.y);
        o0[tid]       = r0.x * scale;  o1[tid]       = r0.y * scale;
        o0[tid + 256] = r1.x * scale;  o1[tid + 256] = r1.y * scale;
        o0[tid + 512] = r2.x * scale;  o1[tid + 512] = r2.y * scale;
        o0[tid + 768] = r3.x * scale;  o1[tid + 768] = r3.y * scale;
    }
}

// ---------------- launch ------------------------------------------------------
extern "C" void kernel_launch(void* const* d_in, const int* in_sizes, int n_in,
                              void* d_out, int out_size)
{
    (void)in_sizes; (void)n_in; (void)out_size;
    const float* x  = (const float*)d_in[0];
    const float* Wq = (const float*)d_in[1];
    const float* Wk = (const float*)d_in[2];
    const float* Wv = (const float*)d_in[3];
    float* out = (float*)d_out;

    cudaFuncSetAttribute(gemm_mma, cudaFuncAttributeMaxDynamicSharedMemorySize, GEMM_SMEM);

    transp_w<<<dim3(32, 32, 3), dim3(32, 8)>>>(Wq, Wk, Wv);
    fft_w<<<(3 * Dv) / 2, 256>>>();
    convert_B<<<NOUT, 256>>>();
    convert_x<<<(NROW * Dv / 4) / 256, 256>>>(x);

    dim3 gg(NOUT / BN, NROW / BM);    // (25, 64)
    gemm_mma<<<gg, 256, GEMM_SMEM>>>();

    spectral_prep<<<NROW, 256>>>();
    scan_pass1<<<dim3(3, NCHK, Bv), 192>>>();
    scan_pass2<<<dim3(3, NCHK, Bv), 192>>>();
    out_kernel<<<NROW / 2, 256>>>(out);
}

// round 17
// speedup vs baseline: 1.0445x; 1.0021x over previous
#include <cuda_runtime.h>
#include <cuda_bf16.h>
#include <cstdint>

#define Bv 4
#define Sv 2048
#define Dv 1024
#define NBv 513
#define KxA 2048           // A = [x_hi | x_lo]
#define Kx 3072            // B K-extent (hi|lo|hi), 48 chunks
#define NOUT 3200          // padded GEMM output width (3*1026 -> 25*128)
#define NROW 8192          // Bv*Sv
#define NCHK 32            // scan chunks (64 rows each)
#define PI_F 3.14159265358979323846f

// ---------------- static device scratch (allocation-free rule) ----------------
__device__ float g_qkv2[(size_t)NROW * NOUT];        // 104.8 MB: spectra q|k|v
__device__ float2 g_kvh[(size_t)NROW * NBv];         // 33.6 MB, [row][bin]; scanned in place
__device__ float2 g_tot[Bv * NCHK * NBv];            // chunk sums
__device__ __align__(16) __nv_bfloat16 g_A2[(size_t)NROW * KxA];     // 32 MB
__device__ __align__(16) __nv_bfloat16 g_B3[(size_t)NOUT * Kx];      // 19.7 MB
__device__ float g_Wt[3 * Dv * Dv];                  // 12.6 MB, W transposed
__device__ float2 g_Bc2[(size_t)3 * NBv * Dv];       // 12.6 MB, What [z][n][d]

__device__ __forceinline__ float2 cmul(float2 a, float2 b) {
    return make_float2(a.x * b.x - a.y * b.y, a.x * b.y + a.y * b.x);
}

__device__ __forceinline__ uint32_t smem_u32(const void* p) {
    uint32_t a;
    asm("{ .reg .u64 t; cvta.to.shared.u64 t, %1; cvt.u32.u64 %0, t; }" : "=r"(a) : "l"(p));
    return a;
}
__device__ __forceinline__ void cp16(uint32_t s, const void* g) {
    asm volatile("cp.async.cg.shared.global [%0], [%1], 16;" :: "r"(s), "l"(g));
}
#define CP_COMMIT() asm volatile("cp.async.commit_group;" ::: "memory")
#define CP_WAIT(n)  asm volatile("cp.async.wait_group %0;" :: "n"(n) : "memory")

__device__ __forceinline__ void mma16816(float* c, const uint32_t* a, const uint32_t* b) {
    asm volatile(
        "mma.sync.aligned.m16n8k16.row.col.f32.bf16.bf16.f32 "
        "{%0,%1,%2,%3}, {%4,%5,%6,%7}, {%8,%9}, {%0,%1,%2,%3};"
        : "+f"(c[0]), "+f"(c[1]), "+f"(c[2]), "+f"(c[3])
        : "r"(a[0]), "r"(a[1]), "r"(a[2]), "r"(a[3]), "r"(b[0]), "r"(b[1]));
}
__device__ __forceinline__ void ldm_x4(uint32_t* r, uint32_t addr) {
    asm volatile("ldmatrix.sync.aligned.m8n8.x4.shared.b16 {%0,%1,%2,%3}, [%4];"
        : "=r"(r[0]), "=r"(r[1]), "=r"(r[2]), "=r"(r[3]) : "r"(addr));
}

// ---------------- 1024-pt radix-4 Stockham FFT in shared memory ---------------
// Stages ST0..ST0+NST-1; caller provides correct in/out buffers.
template<int ST0, int NST>
__device__ __forceinline__ void fft1024_r4(float2* in, float2* out, const float2* TW,
                                           int tid, int inverse)
{
    #pragma unroll
    for (int s = 0; s < NST; s++) {
        const int st = ST0 + s;
        const int Ns = 1 << (2 * st);
        float2 v0 = in[tid];
        float2 v1 = in[tid + 256];
        float2 v2 = in[tid + 512];
        float2 v3 = in[tid + 768];
        const int t = tid & (Ns - 1);
        if (st > 0) {
            const int ti = t << (8 - 2 * st);
            float2 w1 = TW[ti], w2 = TW[2 * ti], w3 = TW[3 * ti];
            if (inverse) { w1.y = -w1.y; w2.y = -w2.y; w3.y = -w3.y; }
            v1 = cmul(v1, w1); v2 = cmul(v2, w2); v3 = cmul(v3, w3);
        }
        float2 a  = make_float2(v0.x + v2.x, v0.y + v2.y);
        float2 bq = make_float2(v0.x - v2.x, v0.y - v2.y);
        float2 c  = make_float2(v1.x + v3.x, v1.y + v3.y);
        float2 d  = make_float2(v1.x - v3.x, v1.y - v3.y);
        float2 dr = inverse ? make_float2(-d.y, d.x) : make_float2(d.y, -d.x);
        const int idx = ((tid >> (2 * st)) << (2 * st + 2)) + t;
        out[idx]          = make_float2(a.x + c.x,  a.y + c.y);
        out[idx + Ns]     = make_float2(bq.x + dr.x, bq.y + dr.y);
        out[idx + 2 * Ns] = make_float2(a.x - c.x,  a.y - c.y);
        out[idx + 3 * Ns] = make_float2(bq.x - dr.x, bq.y - dr.y);
        __syncthreads();
        float2* tmp = in; in = out; out = tmp;
    }
}

__device__ __forceinline__ void fill_tw768(float2* TW, int tid)
{
    for (int t = tid; t < 768; t += 256) {
        float sv, cv;
        __sincosf(-(2.f * PI_F) * (float)t * (1.f / 1024.f), &sv, &cv);
        TW[t] = make_float2(cv, sv);
    }
}

// ================= weight prep: transpose, FFT, bf16 hi/lo ====================
__global__ void transp_w(const float* __restrict__ W0,
                         const float* __restrict__ W1,
                         const float* __restrict__ W2)
{
    __shared__ float t[32][33];
    const float* W = (blockIdx.z == 0) ? W0 : (blockIdx.z == 1) ? W1 : W2;
    const int tx = threadIdx.x, ty = threadIdx.y;
    const int x0 = blockIdx.x * 32, y0 = blockIdx.y * 32;
    #pragma unroll
    for (int j = 0; j < 4; j++)
        t[ty + j * 8][tx] = W[(size_t)(y0 + ty + j * 8) * Dv + x0 + tx];
    __syncthreads();
    float* Wt = g_Wt + (size_t)blockIdx.z * Dv * Dv;
    #pragma unroll
    for (int j = 0; j < 4; j++)
        Wt[(size_t)(x0 + ty + j * 8) * Dv + y0 + tx] = t[tx][ty + j * 8];
}

__global__ void fft_w()
{
    __shared__ float2 bA[1024], bB[1024], TW[768];
    const int tid = threadIdx.x;
    const int row0 = blockIdx.x * 2;
    const int z = row0 >> 10, d0 = row0 & 1023;
    const float* w0 = g_Wt + (size_t)row0 * Dv;
    const float* w1 = w0 + Dv;

    fill_tw768(TW, tid);
    for (int d = tid; d < 1024; d += 256)
        bA[d] = make_float2(w0[d], w1[d]);
    __syncthreads();
    fft1024_r4<0, 5>(bA, bB, TW, tid, 0);      // result in bB

    float2* dst = g_Bc2 + (size_t)z * NBv * Dv;
    for (int n = tid; n < 513; n += 256) {
        float2 z0 = bB[n];
        float2 z1 = bB[(1024 - n) & 1023];
        float2 A = make_float2(0.5f * (z0.x + z1.x), 0.5f * (z0.y - z1.y));
        float2 Bc = make_float2(0.5f * (z0.y + z1.y), 0.5f * (z1.x - z0.x));
        dst[(size_t)n * Dv + d0] = A;
        dst[(size_t)n * Dv + d0 + 1] = Bc;
    }
}

__global__ void convert_B()
{
    const int r = blockIdx.x;
    const int tid = threadIdx.x;
    __nv_bfloat16* row = g_B3 + (size_t)r * Kx;
    if (r >= 3 * 1026) {
        for (int d = tid; d < 1024; d += 256) {
            row[d] = __float2bfloat16_rn(0.f);
            row[1024 + d] = __float2bfloat16_rn(0.f);
            row[2048 + d] = __float2bfloat16_rn(0.f);
        }
        return;
    }
    const int z = r / 1026, rr = r % 1026;
    const int n = rr >> 1, im = rr & 1;
    const float2* src = g_Bc2 + ((size_t)z * NBv + n) * Dv;
    for (int d = tid; d < 1024; d += 256) {
        float2 c = src[d];
        float v = im ? c.y : c.x;
        __nv_bfloat16 h = __float2bfloat16_rn(v);
        __nv_bfloat16 l = __float2bfloat16_rn(v - __bfloat162float(h));
        row[d] = h;
        row[1024 + d] = l;
        row[2048 + d] = h;
    }
}

// A2[m, 0:1024]=hi(x), [1024:2048]=lo(x)
__global__ void convert_x(const float* __restrict__ X)
{
    size_t i4 = (size_t)blockIdx.x * blockDim.x + threadIdx.x;
    float4 x = ((const float4*)X)[i4];
    size_t m = i4 >> 8;
    size_t kc = (i4 & 255) * 4;
    __nv_bfloat16 h0 = __float2bfloat16_rn(x.x), h1 = __float2bfloat16_rn(x.y);
    __nv_bfloat16 h2 = __float2bfloat16_rn(x.z), h3 = __float2bfloat16_rn(x.w);
    __nv_bfloat16 l0 = __float2bfloat16_rn(x.x - __bfloat162float(h0));
    __nv_bfloat16 l1 = __float2bfloat16_rn(x.y - __bfloat162float(h1));
    __nv_bfloat16 l2 = __float2bfloat16_rn(x.z - __bfloat162float(h2));
    __nv_bfloat16 l3 = __float2bfloat16_rn(x.w - __bfloat162float(h3));
    __nv_bfloat16* row = g_A2 + m * KxA;
    __nv_bfloat162 ha = __halves2bfloat162(h0, h1), hb = __halves2bfloat162(h2, h3);
    __nv_bfloat162 la = __halves2bfloat162(l0, l1), lb = __halves2bfloat162(l2, l3);
    *(__nv_bfloat162*)(row + kc) = ha;          *(__nv_bfloat162*)(row + kc + 2) = hb;
    *(__nv_bfloat162*)(row + 1024 + kc) = la;   *(__nv_bfloat162*)(row + 1024 + kc + 2) = lb;
}

// ================= HMMA bf16 GEMM: g_qkv2 = A2(+) @ B3^T ======================
// LOCKED pipeline (round 11/14): CTA 128x128, 256 threads, 3-stage, 2 CTA/SM.
// A source remap only: chunk ch reads A chunk (ch<32 ? ch&15 : ch-16).
#define BM 128
#define BN 128
#define BKC 64
#define NCH (Kx / BKC)        // 48
#define STG_A (BM * 144)      // 18432 B
#define STAGE (2 * STG_A)     // 36864 B (A then B)
#define GEMM_SMEM (3 * STAGE) // 110592 B; 2 CTA/SM

__global__ __launch_bounds__(256, 2) void gemm_mma()
{
    extern __shared__ char smem[];
    const uint32_t sb = smem_u32(smem);
    const int tid = threadIdx.x;
    const int bm = blockIdx.y * BM;
    const int bn = blockIdx.x * BN;

    const int lane = tid & 31, wid = tid >> 5;
    const int g = lane >> 2, tig = lane & 3;
    const int wm = (wid >> 2) * 64, wn = (wid & 3) * 32;

    const int arow = lane & 15;
    const int ahalf = (lane >> 4) & 1;
    const int brow = (lane & 7) + ((lane >> 4) << 3);
    const int bhalf = (lane >> 3) & 1;

    float acc[4][4][4];
    #pragma unroll
    for (int mt = 0; mt < 4; mt++)
        #pragma unroll
        for (int nt = 0; nt < 4; nt++)
            #pragma unroll
            for (int i = 0; i < 4; i++) acc[mt][nt][i] = 0.f;

    auto issue = [&](int ch) {
        const int stg = ch % 3;
        const uint32_t offA = sb + stg * STAGE;
        const uint32_t offB = offA + STG_A;
        const int aIdx = (ch < 32) ? (ch & 15) : (ch - 16);   // A chunk in [0,32)
        const size_t koffA = (size_t)aIdx * BKC;
        const size_t koffB = (size_t)ch * BKC;
        #pragma unroll
        for (int t = 0; t < 4; t++) {
            int idx = tid + t * 256;
            int r = idx >> 3, c = idx & 7;
            cp16(offA + r * 144 + c * 16, g_A2 + (size_t)(bm + r) * KxA + koffA + c * 8);
        }
        #pragma unroll
        for (int t = 0; t < 4; t++) {
            int idx = tid + t * 256;
            int r = idx >> 3, c = idx & 7;
            cp16(offB + r * 144 + c * 16, g_B3 + (size_t)(bn + r) * Kx + koffB + c * 8);
        }
        CP_COMMIT();
    };

    issue(0);
    issue(1);
    for (int ch = 0; ch < NCH; ch++) {
        if (ch + 1 < NCH) { CP_WAIT(1); } else { CP_WAIT(0); }
        __syncthreads();                       // single barrier per chunk

        const int stg = ch % 3;
        const uint32_t sA32 = sb + stg * STAGE;
        const uint32_t sB32 = sA32 + STG_A;
        #pragma unroll
        for (int ks = 0; ks < 4; ks++) {
            uint32_t af[4][4], bfr[2][4];
            #pragma unroll
            for (int mt = 0; mt < 4; mt++)
                ldm_x4(af[mt], sA32 + (wm + mt * 16 + arow) * 144 + ks * 32 + ahalf * 16);
            #pragma unroll
            for (int np = 0; np < 2; np++)
                ldm_x4(bfr[np], sB32 + (wn + np * 16 + brow) * 144 + ks * 32 + bhalf * 16);
            #pragma unroll
            for (int mt = 0; mt < 4; mt++)
                #pragma unroll
                for (int nt = 0; nt < 4; nt++)
                    mma16816(acc[mt][nt], af[mt], &bfr[nt >> 1][(nt & 1) * 2]);
        }

        if (ch + 2 < NCH) issue(ch + 2);       // writes stage (ch+2)%3: disjoint
    }

    #pragma unroll
    for (int mt = 0; mt < 4; mt++) {
        #pragma unroll
        for (int nt = 0; nt < 4; nt++) {
            int row = bm + wm + mt * 16 + g;
            int col = bn + wn + nt * 8 + 2 * tig;
            *(float2*)(g_qkv2 + (size_t)row * NOUT + col) =
                make_float2(acc[mt][nt][0], acc[mt][nt][1]);
            *(float2*)(g_qkv2 + (size_t)(row + 8) * NOUT + col) =
                make_float2(acc[mt][nt][2], acc[mt][nt][3]);
        }
    }
}

// ---------------- spectral prep: K,V only -> kvhat (coalesced) ----------------
__global__ void spectral_prep()
{
    const int row = blockIdx.x;                 // b*2048 + s
    const int tid = threadIdx.x;
    const float2* base = (const float2*)(g_qkv2 + (size_t)row * NOUT);
    const float2* kr = base + 513;
    const float2* vr = base + 1026;
    float2* kvout = g_kvh + (size_t)row * NBv;

    for (int n = tid; n < 513; n += 256) {
        float2 K = kr[n], V = vr[n];
        float ik = 1.f / (sqrtf(K.x * K.x + K.y * K.y) + 1e-8f);
        float2 Ku = make_float2(K.x * ik, K.y * ik);
        kvout[n] = cmul(Ku, V);
    }
}

// ---------------- chunked scan along s (layout [row][bin], 64-row chunks) -----
__global__ void scan_pass1()
{
    const int tid = threadIdx.x;
    if (tid >= 171) return;
    const int bin = blockIdx.x * 171 + tid;     // 3*171 = 513
    const int chunk = blockIdx.y, b = blockIdx.z;
    const float2* p = g_kvh + ((size_t)(b * Sv + chunk * 64)) * NBv + bin;
    float2 acc = make_float2(0.f, 0.f);
    #pragma unroll 4
    for (int r = 0; r < 64; r++) {
        float2 v = *p;
        acc.x += v.x; acc.y += v.y;
        p += NBv;
    }
    g_tot[((size_t)b * NCHK + chunk) * NBv + bin] = acc;
}

// pass2: walk chunk adding prefix, write scanned value IN PLACE into g_kvh
__global__ void scan_pass2()
{
    const int tid = threadIdx.x;
    if (tid >= 171) return;
    const int bin = blockIdx.x * 171 + tid;
    const int chunk = blockIdx.y, b = blockIdx.z;

    float2 acc = make_float2(0.f, 0.f);
    for (int c = 0; c < chunk; c++) {
        float2 t = g_tot[((size_t)b * NCHK + c) * NBv + bin];
        acc.x += t.x; acc.y += t.y;
    }
    float2* p = g_kvh + ((size_t)(b * Sv + chunk * 64)) * NBv + bin;
    #pragma unroll 4
    for (int r = 0; r < 64; r++) {
        float2 v = *p;
        acc.x += v.x; acc.y += v.y;
        *p = acc;
        p += NBv;
    }
}

// ------- inverse FFT: inline conj-norm Q, reg stage-0 + reg finale ------------
__global__ void out_kernel(float* __restrict__ out)
{
    __shared__ float2 bA[1024], bB[1024], TW[768];
    const int tid = threadIdx.x;
    const int row0 = blockIdx.x * 2;

    fill_tw768(TW, tid);
    const float2* kv0 = g_kvh + (size_t)row0 * NBv;
    const float2* kv1 = kv0 + NBv;
    const float2* q0 = (const float2*)(g_qkv2 + (size_t)row0 * NOUT);
    const float2* q1 = (const float2*)(g_qkv2 + (size_t)(row0 + 1) * NOUT);

    // Load 4 elements (d = tid + k*256), build Z = X0 + i*X1 in registers
    float2 v[4];
    #pragma unroll
    for (int k = 0; k < 4; k++) {
        const int d = tid + k * 256;
        const int n = (d <= 512) ? d : 1024 - d;
        float2 kA = kv0[n], qA = q0[n];
        float2 kB = kv1[n], qB = q1[n];
        float iA = 1.f / (sqrtf(qA.x * qA.x + qA.y * qA.y) + 1e-8f);
        float iB = 1.f / (sqrtf(qB.x * qB.x + qB.y * qB.y) + 1e-8f);
        float2 x0 = cmul(kA, make_float2(qA.x * iA, -qA.y * iA));
        float2 x1 = cmul(kB, make_float2(qB.x * iB, -qB.y * iB));
        if (d > 512) { x0.y = -x0.y; x1.y = -x1.y; }     // Hermitian extension
        v[k] = make_float2(x0.x - x1.y, x0.y + x1.x);
    }
    // Stage 0 (Ns=1, no twiddles) in registers, write to bB[4*tid + i]
    {
        float2 a  = make_float2(v[0].x + v[2].x, v[0].y + v[2].y);
        float2 bq = make_float2(v[0].x - v[2].x, v[0].y - v[2].y);
        float2 c  = make_float2(v[1].x + v[3].x, v[1].y + v[3].y);
        float2 d  = make_float2(v[1].x - v[3].x, v[1].y - v[3].y);
        float2 dr = make_float2(-d.y, d.x);              // inverse rotation
        bB[4 * tid]     = make_float2(a.x + c.x,  a.y + c.y);
        bB[4 * tid + 1] = make_float2(bq.x + dr.x, bq.y + dr.y);
        bB[4 * tid + 2] = make_float2(a.x - c.x,  a.y - c.y);
        bB[4 * tid + 3] = make_float2(bq.x - dr.x, bq.y - dr.y);
    }
    __syncthreads();
    // Stages 1..3 in smem: bB -> bA -> bB -> bA (result in bA)
    fft1024_r4<1, 3>(bB, bA, TW, tid, 1);

    // final stage (st=4, Ns=256) in registers, write gmem directly
    float* o0 = out + (size_t)row0 * Dv;
    float* o1 = o0 + Dv;
    const float scale = 1.f / 1024.f;
    {
        float2 v0 = bA[tid], v1 = bA[tid + 256], v2 = bA[tid + 512], v3 = bA[tid + 768];
        float2 w1 = TW[tid], w2 = TW[2 * tid], w3 = TW[3 * tid];
        w1.y = -w1.y; w2.y = -w2.y; w3.y = -w3.y;        // inverse twiddles
        v1 = cmul(v1, w1); v2 = cmul(v2, w2); v3 = cmul(v3, w3);
        float2 a  = make_float2(v0.x + v2.x, v0.y + v2.y);
        float2 bq = make_float2(v0.x - v2.x, v0.y - v2.y);
        float2 c  = make_float2(v1.x + v3.x, v1.y + v3.y);
        float2 d  = make_float2(v1.x - v3.x, v1.y - v3.y);
        float2 dr = make_float2(-d.y, d.x);              // inverse rotation
        float2 r0 = make_float2(a.x + c.x,  a.y + c.y);
        float2 r1 = make_float2(bq.x + dr.x, bq.y + dr.y);
        float2 r2 = make_float2(a.x - c.x,  a.y - c.y);
        float2 r3 = make_float2(bq.x - dr.x, bq.y - dr.y);
        o0[tid]       = r0.x * scale;  o1[tid]       = r0.y * scale;
        o0[tid + 256] = r1.x * scale;  o1[tid + 256] = r1.y * scale;
        o0[tid + 512] = r2.x * scale;  o1[tid + 512] = r2.y * scale;
        o0[tid + 768] = r3.x * scale;  o1[tid + 768] = r3.y * scale;
    }
}

// ---------------- launch ------------------------------------------------------
extern "C" void kernel_launch(void* const* d_in, const int* in_sizes, int n_in,
                              void* d_out, int out_size)
{
    (void)in_sizes; (void)n_in; (void)out_size;
    const float* x  = (const float*)d_in[0];
    const float* Wq = (const float*)d_in[1];
    const float* Wk = (const float*)d_in[2];
    const float* Wv = (const float*)d_in[3];
    float* out = (float*)d_out;

    cudaFuncSetAttribute(gemm_mma, cudaFuncAttributeMaxDynamicSharedMemorySize, GEMM_SMEM);

    transp_w<<<dim3(32, 32, 3), dim3(32, 8)>>>(Wq, Wk, Wv);
    fft_w<<<(3 * Dv) / 2, 256>>>();
    convert_B<<<NOUT, 256>>>();
    convert_x<<<(NROW * Dv / 4) / 256, 256>>>(x);

    dim3 gg(NOUT / BN, NROW / BM);    // (25, 64)
    gemm_mma<<<gg, 256, GEMM_SMEM>>>();

    spectral_prep<<<NROW, 256>>>();
    scan_pass1<<<dim3(3, NCHK, Bv), 192>>>();
    scan_pass2<<<dim3(3, NCHK, Bv), 192>>>();
    out_kernel<<<NROW / 2, 256>>>(out);
}